// round 1
// baseline (speedup 1.0000x reference)
#include <cuda_runtime.h>
#include <cstddef>

#define NEGF (-10000.0f)
constexpr int S_LEN = 1024;
constexpr int NLAB  = 49;
constexpr int L     = 51;   // NL + 2; start = 49, end = 50

// 51-long dot product in f32x2 packed FMA. pv points to 52 floats (16B aligned,
// element 51 is always 0), eTp holds 26 packed f32x2 (row of exp(T), padded 0).
__device__ __forceinline__ float dot51(const float4* __restrict__ pv,
                                       const unsigned long long* __restrict__ eTp)
{
    unsigned long long a0 = 0ull, a1 = 0ull;
    #pragma unroll
    for (int q = 0; q < 13; q++) {
        float4 v = pv[q];
        unsigned long long p01, p23;
        asm("mov.b64 %0, {%1, %2};" : "=l"(p01) : "f"(v.x), "f"(v.y));
        asm("mov.b64 %0, {%1, %2};" : "=l"(p23) : "f"(v.z), "f"(v.w));
        asm("fma.rn.f32x2 %0, %1, %2, %0;" : "+l"(a0) : "l"(p01), "l"(eTp[2*q]));
        asm("fma.rn.f32x2 %0, %1, %2, %0;" : "+l"(a1) : "l"(p23), "l"(eTp[2*q+1]));
    }
    float s0, s1, s2, s3;
    asm("mov.b64 {%0, %1}, %2;" : "=f"(s0), "=f"(s1) : "l"(a0));
    asm("mov.b64 {%0, %1}, %2;" : "=f"(s2), "=f"(s3) : "l"(a1));
    return (s0 + s1) + (s2 + s3);
}

__global__ __launch_bounds__(64) void crf_fwd_kernel(
    const float* __restrict__ logits,   // [B, S, NL]
    const float* __restrict__ trans,    // [L, L]
    const int*   __restrict__ labels,   // [B, S]
    const int*   __restrict__ lens,     // [B]
    float*       __restrict__ out)      // [B]
{
    __shared__ float Ts[L * L];
    __shared__ __align__(16) float pbuf[2][52];
    __shared__ float xsh[2];
    __shared__ float red[64];
    __shared__ float norm_sh;

    const int b   = blockIdx.x;
    const int tid = threadIdx.x;
    const int len = lens[b];

    // stage raw transition (also used for gold binary lookups)
    for (int i = tid; i < L * L; i += 64) Ts[i] = trans[i];
    if (tid < 52) {
        pbuf[0][tid] = (tid == L - 2) ? 1.0f : 0.0f;  // alpha0: start=0 -> p=1
        pbuf[1][tid] = 0.0f;
    }
    if (tid < 2) xsh[tid] = 0.0f;
    __syncthreads();

    // per-thread exp(T[j, :]) row, packed f32x2 (rows for tid>=51 are zero)
    unsigned long long eTp[26];
    #pragma unroll
    for (int q = 0; q < 26; q++) {
        float a = 0.0f, c = 0.0f;
        if (tid < L) {
            int k = 2 * q;
            a = __expf(Ts[tid * L + k]);
            if (k + 1 < L) c = __expf(Ts[tid * L + k + 1]);
        }
        asm("mov.b64 %0, {%1, %2};" : "=l"(eTp[q]) : "f"(a), "f"(c));
    }

    // logits prefetch ring (depth 4)
    const float* lp = logits + (size_t)b * S_LEN * NLAB + tid;
    float lgf[4];
    #pragma unroll
    for (int i = 0; i < 4; i++)
        lgf[i] = (tid < NLAB) ? __ldg(lp + i * NLAB) : NEGF;

    double C = 0.0;   // accumulated normalization offset
    float  r = 0.0f;  // previous step's x[0]

    #pragma unroll 4
    for (int t = 0; t < len; t++) {
        const int cur = t & 1;
        const float lg = lgf[t & 3];
        const int tp = t + 4;
        if (tid < NLAB && tp < len)
            lgf[t & 3] = __ldg(lp + (size_t)tp * NLAB);

        float Ssum = dot51(reinterpret_cast<const float4*>(pbuf[cur]), eTp);

        float x  = lg + __logf(Ssum);          // alpha_next[j] - C
        float pn = __expf(x - r);              // new normalized prob
        if (tid < L)  pbuf[cur ^ 1][tid] = pn;
        if (tid == 0) xsh[cur ^ 1] = x;
        C += (double)r;
        __syncthreads();
        r = xsh[cur ^ 1];
    }

    // norm = C + log( sum_k p[k] * exp(T[end, k]) )  -- thread 50 owns row 'end'
    {
        float Ssum = dot51(reinterpret_cast<const float4*>(pbuf[len & 1]), eTp);
        if (tid == L - 1)
            norm_sh = (float)(C + (double)__logf(Ssum));
    }

    // gold = unary + binary (parallel gather over t)
    const int* labp = labels + (size_t)b * S_LEN;
    float acc = 0.0f;
    #pragma unroll 4
    for (int t = tid; t < len; t += 64) {
        int lab = labp[t];
        acc += __ldg(logits + ((size_t)b * S_LEN + t) * NLAB + lab);
        int prev = (t == 0) ? (L - 2) : labp[t - 1];
        acc += Ts[lab * L + prev];
    }
    if (tid == 0) acc += Ts[(L - 1) * L + labp[len - 1]];  // T[end, last label]
    red[tid] = acc;
    __syncthreads();

    if (tid < 32) {
        float v = red[tid] + red[tid + 32];
        #pragma unroll
        for (int o = 16; o; o >>= 1) v += __shfl_down_sync(0xffffffffu, v, o);
        if (tid == 0) out[b] = v - norm_sh;
    }
}

extern "C" void kernel_launch(void* const* d_in, const int* in_sizes, int n_in,
                              void* d_out, int out_size)
{
    const float* logits = (const float*)d_in[0];
    const float* trans  = (const float*)d_in[1];
    const int*   labels = (const int*)d_in[2];
    const int*   lens   = (const int*)d_in[3];
    const int B = in_sizes[3];
    crf_fwd_kernel<<<B, 64>>>(logits, trans, labels, lens, (float*)d_out);
}

// round 2
// speedup vs baseline: 1.0024x; 1.0024x over previous
#include <cuda_runtime.h>
#include <cstddef>

#define NEGF (-10000.0f)
constexpr int S_LEN = 1024;
constexpr int NLAB  = 49;
constexpr int L     = 51;   // NL + 2; start = 49, end = 50

// 51-long dot product in f32x2 packed FMA. pv points to 52 floats (16B aligned,
// element 51 is always 0), eTp holds 26 packed f32x2 (row of exp(T), padded 0).
__device__ __forceinline__ float dot51(const float4* __restrict__ pv,
                                       const unsigned long long* __restrict__ eTp)
{
    unsigned long long a0 = 0ull, a1 = 0ull;
    #pragma unroll
    for (int q = 0; q < 13; q++) {
        float4 v = pv[q];
        unsigned long long p01, p23;
        asm("mov.b64 %0, {%1, %2};" : "=l"(p01) : "f"(v.x), "f"(v.y));
        asm("mov.b64 %0, {%1, %2};" : "=l"(p23) : "f"(v.z), "f"(v.w));
        asm("fma.rn.f32x2 %0, %1, %2, %0;" : "+l"(a0) : "l"(p01), "l"(eTp[2*q]));
        asm("fma.rn.f32x2 %0, %1, %2, %0;" : "+l"(a1) : "l"(p23), "l"(eTp[2*q+1]));
    }
    float s0, s1, s2, s3;
    asm("mov.b64 {%0, %1}, %2;" : "=f"(s0), "=f"(s1) : "l"(a0));
    asm("mov.b64 {%0, %1}, %2;" : "=f"(s2), "=f"(s3) : "l"(a1));
    return (s0 + s1) + (s2 + s3);
}

__global__ __launch_bounds__(64) void crf_fwd_kernel(
    const float* __restrict__ logits,   // [B, S, NL]
    const float* __restrict__ trans,    // [L, L]
    const int*   __restrict__ labels,   // [B, S]
    const int*   __restrict__ lens,     // [B]
    float*       __restrict__ out)      // [B]
{
    __shared__ float Ts[L * L];
    __shared__ __align__(16) float pbuf[2][52];
    __shared__ float xsh[2];
    __shared__ float red[64];
    __shared__ float norm_sh;

    const int b   = blockIdx.x;
    const int tid = threadIdx.x;
    const int len = lens[b];

    // stage raw transition (also used for gold binary lookups)
    for (int i = tid; i < L * L; i += 64) Ts[i] = trans[i];
    if (tid < 52) {
        pbuf[0][tid] = (tid == L - 2) ? 1.0f : 0.0f;  // alpha0: start=0 -> p=1
        pbuf[1][tid] = 0.0f;
    }
    if (tid < 2) xsh[tid] = 0.0f;
    __syncthreads();

    // per-thread exp(T[j, :]) row, packed f32x2 (rows for tid>=51 are zero)
    unsigned long long eTp[26];
    #pragma unroll
    for (int q = 0; q < 26; q++) {
        float a = 0.0f, c = 0.0f;
        if (tid < L) {
            int k = 2 * q;
            a = __expf(Ts[tid * L + k]);
            if (k + 1 < L) c = __expf(Ts[tid * L + k + 1]);
        }
        asm("mov.b64 %0, {%1, %2};" : "=l"(eTp[q]) : "f"(a), "f"(c));
    }

    // logits prefetch ring (depth 4)
    const float* lp = logits + (size_t)b * S_LEN * NLAB + tid;
    float lgf[4];
    #pragma unroll
    for (int i = 0; i < 4; i++)
        lgf[i] = (tid < NLAB) ? __ldg(lp + i * NLAB) : NEGF;

    double C = 0.0;   // accumulated normalization offset
    float  r = 0.0f;  // previous step's x[0]

    #pragma unroll 4
    for (int t = 0; t < len; t++) {
        const int cur = t & 1;
        const float lg = lgf[t & 3];
        const int tp = t + 4;
        if (tid < NLAB && tp < len)
            lgf[t & 3] = __ldg(lp + (size_t)tp * NLAB);

        float Ssum = dot51(reinterpret_cast<const float4*>(pbuf[cur]), eTp);

        float x  = lg + __logf(Ssum);          // alpha_next[j] - C
        float pn = __expf(x - r);              // new normalized prob
        if (tid < L)  pbuf[cur ^ 1][tid] = pn;
        if (tid == 0) xsh[cur ^ 1] = x;
        C += (double)r;
        __syncthreads();
        r = xsh[cur ^ 1];
    }

    // norm = C + log( sum_k p[k] * exp(T[end, k]) )  -- thread 50 owns row 'end'
    {
        float Ssum = dot51(reinterpret_cast<const float4*>(pbuf[len & 1]), eTp);
        if (tid == L - 1)
            norm_sh = (float)(C + (double)__logf(Ssum));
    }

    // gold = unary + binary (parallel gather over t)
    const int* labp = labels + (size_t)b * S_LEN;
    float acc = 0.0f;
    #pragma unroll 4
    for (int t = tid; t < len; t += 64) {
        int lab = labp[t];
        acc += __ldg(logits + ((size_t)b * S_LEN + t) * NLAB + lab);
        int prev = (t == 0) ? (L - 2) : labp[t - 1];
        acc += Ts[lab * L + prev];
    }
    if (tid == 0) acc += Ts[(L - 1) * L + labp[len - 1]];  // T[end, last label]
    red[tid] = acc;
    __syncthreads();

    if (tid < 32) {
        float v = red[tid] + red[tid + 32];
        #pragma unroll
        for (int o = 16; o; o >>= 1) v += __shfl_down_sync(0xffffffffu, v, o);
        if (tid == 0) out[b] = v - norm_sh;
    }
}

extern "C" void kernel_launch(void* const* d_in, const int* in_sizes, int n_in,
                              void* d_out, int out_size)
{
    const float* logits = (const float*)d_in[0];
    const float* trans  = (const float*)d_in[1];
    const int*   labels = (const int*)d_in[2];
    const int*   lens   = (const int*)d_in[3];
    const int B = in_sizes[3];
    crf_fwd_kernel<<<B, 64>>>(logits, trans, labels, lens, (float*)d_out);
}

// round 3
// speedup vs baseline: 1.1776x; 1.1748x over previous
#include <cuda_runtime.h>
#include <cstddef>

#define NEGF (-10000.0f)
constexpr int S_LEN = 1024;
constexpr int NLAB  = 49;
constexpr int L     = 51;   // start = 49, end = 50

__device__ __forceinline__ unsigned long long pk2(float a, float b) {
    unsigned long long r;
    asm("mov.b64 %0, {%1, %2};" : "=l"(r) : "f"(a), "f"(b));
    return r;
}
__device__ __forceinline__ void upk2(unsigned long long v, float& a, float& b) {
    asm("mov.b64 {%0, %1}, %2;" : "=f"(a), "=f"(b) : "l"(v));
}

__global__ __launch_bounds__(32) void crf_fwd_kernel(
    const float* __restrict__ logits,   // [B, S, NL]
    const float* __restrict__ trans,    // [L, L]
    const int*   __restrict__ labels,   // [B, S]
    const int*   __restrict__ lens,     // [B]
    float*       __restrict__ out)      // [B]
{
    __shared__ __align__(16) float qsh[2][56];   // q double buffer, slot 51..55 = 0

    const int b    = blockIdx.x;
    const int lane = threadIdx.x;
    const int len  = lens[b];

    // ---- per-lane exp(T) rows: lo = state lane, hi = state lane+32 ----
    unsigned long long eLo[26], eHi[26];
    {
        const float* rlo = trans + lane * L;
        const float* rhi = trans + (lane + 32) * L;
        const bool hasHi = (lane + 32) < L;          // lanes 0..18
        #pragma unroll
        for (int q = 0; q < 26; q++) {
            int k = 2 * q;
            float a = __expf(rlo[k]);
            float c = (k + 1 < L) ? __expf(rlo[k + 1]) : 0.0f;
            eLo[q] = pk2(a, c);
            float d = 0.0f, e = 0.0f;
            if (hasHi) {
                d = __expf(rhi[k]);
                if (k + 1 < L) e = __expf(rhi[k + 1]);
            }
            eHi[q] = pk2(d, e);
        }
    }

    // ---- init q0: all zero, q0[start=49] = 1 ----
    for (int i = lane; i < 56; i += 32) { qsh[0][i] = 0.0f; qsh[1][i] = 0.0f; }
    __syncwarp();
    if (lane == 17) qsh[0][49] = 1.0f;   // state 49 = hi slot of lane 17
    __syncwarp();

    // ---- logits prefetch ring (depth 8) ----
    const float* lp = logits + (size_t)b * S_LEN * NLAB;
    const bool hasHiLg = (lane + 32) < NLAB;          // lanes 0..16 (states 49,50 -> NEG)
    float rl[8], rh[8];
    #pragma unroll
    for (int i = 0; i < 8; i++) {
        rl[i] = __ldg(lp + (size_t)i * NLAB + lane);
        rh[i] = hasHiLg ? __ldg(lp + (size_t)i * NLAB + lane + 32) : NEGF;
    }

    // pipeline state entering step 0
    float lg0cur = __shfl_sync(0xffffffffu, rl[0], 0);
    float vlo = __expf(rl[0] - lg0cur);
    float vhi = hasHiLg ? __expf(rh[0] - lg0cur) : 0.0f;
    float rcp_prev = 1.0f;     // 1/S_{-1}[0]
    double D = 0.0;            // log-offset accumulator

    for (int tb = 0; tb < len; tb += 8) {
        #pragma unroll
        for (int i = 0; i < 8; i++) {
            const int t = tb + i;
            if (t >= len) break;
            const int par = i & 1;

            float ulo = vlo * rcp_prev;
            float uhi = vhi * rcp_prev;

            // --- critical path: dot over q_t (2 chains per state) ---
            unsigned long long a0 = 0ull, a1 = 0ull, b0 = 0ull, b1 = 0ull;
            const ulonglong2* qp = reinterpret_cast<const ulonglong2*>(qsh[par]);
            #pragma unroll
            for (int q2 = 0; q2 < 13; q2++) {
                ulonglong2 qq = qp[q2];
                asm("fma.rn.f32x2 %0, %1, %2, %0;" : "+l"(a0) : "l"(qq.x), "l"(eLo[2*q2]));
                asm("fma.rn.f32x2 %0, %1, %2, %0;" : "+l"(a1) : "l"(qq.y), "l"(eLo[2*q2+1]));
                asm("fma.rn.f32x2 %0, %1, %2, %0;" : "+l"(b0) : "l"(qq.x), "l"(eHi[2*q2]));
                asm("fma.rn.f32x2 %0, %1, %2, %0;" : "+l"(b1) : "l"(qq.y), "l"(eHi[2*q2+1]));
            }

            // --- off-path: v for step t+1 + prefetch t+8 ---
            const int ni = (i + 1) & 7;
            float lg0n = __shfl_sync(0xffffffffu, rl[ni], 0);
            float vloN = __expf(rl[ni] - lg0n);
            float vhiN = hasHiLg ? __expf(rh[ni] - lg0n) : 0.0f;
            if (t + 8 < S_LEN) {
                rl[i] = __ldg(lp + (size_t)(t + 8) * NLAB + lane);
                if (hasHiLg) rh[i] = __ldg(lp + (size_t)(t + 8) * NLAB + lane + 32);
            }

            unsigned long long asum, bsum;
            asm("add.rn.f32x2 %0, %1, %2;" : "=l"(asum) : "l"(a0), "l"(a1));
            asm("add.rn.f32x2 %0, %1, %2;" : "=l"(bsum) : "l"(b0), "l"(b1));
            float s0, s1, s2, s3;
            upk2(asum, s0, s1);
            upk2(bsum, s2, s3);
            float Slo = s0 + s1;
            float Shi = s2 + s3;

            // off-path: next reciprocal + log-offset bookkeeping
            float S0 = __shfl_sync(0xffffffffu, Slo, 0);
            float rcpn;
            asm("rcp.approx.f32 %0, %1;" : "=f"(rcpn) : "f"(S0));
            D += (double)(lg0cur - __logf(rcp_prev));   // exact vs applied scale

            // --- critical path: store q_{t+1} ---
            qsh[par ^ 1][lane] = Slo * ulo;
            if (lane < 19) qsh[par ^ 1][lane + 32] = Shi * uhi;
            __syncwarp();

            rcp_prev = rcpn; vlo = vloN; vhi = vhiN; lg0cur = lg0n;
        }
    }

    // ---- norm = D + log( Σ_k q_len[k] * eT[end=50, k] )  (row 50 = hi of lane 18) ----
    float normf;
    {
        const int par = len & 1;
        unsigned long long b0 = 0ull, b1 = 0ull;
        const ulonglong2* qp = reinterpret_cast<const ulonglong2*>(qsh[par]);
        #pragma unroll
        for (int q2 = 0; q2 < 13; q2++) {
            ulonglong2 qq = qp[q2];
            asm("fma.rn.f32x2 %0, %1, %2, %0;" : "+l"(b0) : "l"(qq.x), "l"(eHi[2*q2]));
            asm("fma.rn.f32x2 %0, %1, %2, %0;" : "+l"(b1) : "l"(qq.y), "l"(eHi[2*q2+1]));
        }
        unsigned long long bsum;
        asm("add.rn.f32x2 %0, %1, %2;" : "=l"(bsum) : "l"(b0), "l"(b1));
        float s2, s3;
        upk2(bsum, s2, s3);
        float Send = s2 + s3;
        float nf = (float)(D + (double)__logf(Send));
        normf = __shfl_sync(0xffffffffu, nf, 18);
    }

    // ---- gold = unary + binary (parallel gather) ----
    const int* labp = labels + (size_t)b * S_LEN;
    float acc = 0.0f;
    #pragma unroll 4
    for (int t = lane; t < len; t += 32) {
        int lab = labp[t];
        acc += __ldg(lp + (size_t)t * NLAB + lab);
        int prev = t ? labp[t - 1] : (L - 2);
        acc += __ldg(trans + lab * L + prev);
    }
    if (lane == 0) acc += __ldg(trans + (L - 1) * L + labp[len - 1]);
    #pragma unroll
    for (int o = 16; o; o >>= 1) acc += __shfl_down_sync(0xffffffffu, acc, o);

    if (lane == 0) out[b] = acc - normf;
}

extern "C" void kernel_launch(void* const* d_in, const int* in_sizes, int n_in,
                              void* d_out, int out_size)
{
    const float* logits = (const float*)d_in[0];
    const float* trans  = (const float*)d_in[1];
    const int*   labels = (const int*)d_in[2];
    const int*   lens   = (const int*)d_in[3];
    const int B = in_sizes[3];
    crf_fwd_kernel<<<B, 32>>>(logits, trans, labels, lens, (float*)d_out);
}

// round 4
// speedup vs baseline: 1.5383x; 1.3063x over previous
#include <cuda_runtime.h>
#include <cstddef>

#define NEGF (-10000.0f)
constexpr int S_LEN = 1024;
constexpr int NLAB  = 49;
constexpr int L     = 51;   // start = 49, end = 50

__device__ __forceinline__ unsigned long long pk2(float a, float b) {
    unsigned long long r;
    asm("mov.b64 %0, {%1, %2};" : "=l"(r) : "f"(a), "f"(b));
    return r;
}
__device__ __forceinline__ void upk2(unsigned long long v, float& a, float& b) {
    asm("mov.b64 {%0, %1}, %2;" : "=f"(a), "=f"(b) : "l"(v));
}

// 50-term dot (k = 0..49) over q in shared, 4 accumulator chains.
// qp = 13 x ulonglong2 (56 floats, 50..55 zero / unused k>=50 dropped).
#define DOT50(EARR, OUT)                                                         \
    do {                                                                         \
        unsigned long long c0 = 0ull, c1 = 0ull, c2 = 0ull, c3 = 0ull;           \
        _Pragma("unroll")                                                        \
        for (int q2 = 0; q2 < 12; q2 += 2) {                                     \
            ulonglong2 qa = qp[q2], qb = qp[q2 + 1];                             \
            asm("fma.rn.f32x2 %0, %1, %2, %0;" : "+l"(c0) : "l"(qa.x), "l"(EARR[2*q2]));     \
            asm("fma.rn.f32x2 %0, %1, %2, %0;" : "+l"(c1) : "l"(qa.y), "l"(EARR[2*q2+1]));   \
            asm("fma.rn.f32x2 %0, %1, %2, %0;" : "+l"(c2) : "l"(qb.x), "l"(EARR[2*q2+2]));   \
            asm("fma.rn.f32x2 %0, %1, %2, %0;" : "+l"(c3) : "l"(qb.y), "l"(EARR[2*q2+3]));   \
        }                                                                        \
        {                                                                        \
            ulonglong2 qa = qp[12]; /* floats 48..51; only x (k=48,49) nonzero */\
            asm("fma.rn.f32x2 %0, %1, %2, %0;" : "+l"(c0) : "l"(qa.x), "l"(EARR[24]));       \
        }                                                                        \
        unsigned long long s01, s23, sall;                                       \
        asm("add.rn.f32x2 %0, %1, %2;" : "=l"(s01) : "l"(c0), "l"(c1));          \
        asm("add.rn.f32x2 %0, %1, %2;" : "=l"(s23) : "l"(c2), "l"(c3));          \
        asm("add.rn.f32x2 %0, %1, %2;" : "=l"(sall) : "l"(s01), "l"(s23));       \
        float z0, z1;                                                            \
        upk2(sall, z0, z1);                                                      \
        OUT = z0 + z1;                                                           \
    } while (0)

__global__ __launch_bounds__(32) void crf_fwd_kernel(
    const float* __restrict__ logits,   // [B, S, NL]
    const float* __restrict__ trans,    // [L, L]
    const int*   __restrict__ labels,   // [B, S]
    const int*   __restrict__ lens,     // [B]
    float*       __restrict__ out)      // [B]
{
    __shared__ __align__(16) float qsh[2][56];   // q double buffer; 51..55 = 0

    const int b    = blockIdx.x;
    const int lane = threadIdx.x;
    const int len  = lens[b];

    // ---- per-lane exp(T) rows (k = 0..49 packed as 25 f32x2) ----
    // lo = state 'lane', hi = state 'lane+32' (valid for lanes 0..18)
    unsigned long long eLo[25], eHi[25];
    {
        const float* rlo = trans + lane * L;
        const float* rhi = trans + (lane + 32) * L;
        const bool hasHi = (lane + 32) < L;
        #pragma unroll
        for (int q = 0; q < 25; q++) {
            int k = 2 * q;
            eLo[q] = pk2(__expf(rlo[k]), __expf(rlo[k + 1]));
            float d = 0.0f, e = 0.0f;
            if (hasHi) { d = __expf(rhi[k]); e = __expf(rhi[k + 1]); }
            eHi[q] = pk2(d, e);
        }
    }

    // ---- init q0: zero except q0[start=49] = 1 (hi slot of lane 17) ----
    for (int i = lane; i < 56; i += 32) { qsh[0][i] = 0.0f; qsh[1][i] = 0.0f; }
    __syncwarp();
    if (lane == 17) qsh[0][49] = 1.0f;
    __syncwarp();

    // ---- logits prefetch ring (depth 8) ----
    const float* lp = logits + (size_t)b * S_LEN * NLAB;
    const bool hasHiLg = (lane + 32) < NLAB;   // lanes 0..16
    float rl[8], rh[8];
    #pragma unroll
    for (int i = 0; i < 8; i++) {
        rl[i] = __ldg(lp + (size_t)i * NLAB + lane);
        rh[i] = hasHiLg ? __ldg(lp + (size_t)i * NLAB + lane + 32) : NEGF;
    }

    float sc    = 1.0f;   // scale applied this step (power of two)
    int   eprev = 0;      // exponent of that scale (negated sign handled below)
    int   Eacc  = 0;      // sum of applied exponents (exact)

    for (int tb = 0; tb < len; tb += 8) {
        // hoisted off-path: v = exp(logit) for the whole block (pipelined MUFU)
        float vl[8], vh[8];
        #pragma unroll
        for (int i = 0; i < 8; i++) {
            vl[i] = __expf(rl[i]);
            vh[i] = hasHiLg ? __expf(rh[i]) : 0.0f;
        }

        #pragma unroll
        for (int i = 0; i < 8; i++) {
            const int t = tb + i;
            if (t >= len) break;
            const int par = i & 1;   // == t & 1 since tb % 8 == 0

            float ulo = vl[i] * sc;
            float uhi = vh[i] * sc;

            // prefetch row t+8 into the slot just consumed
            if (t + 8 < S_LEN) {
                rl[i] = __ldg(lp + (size_t)(t + 8) * NLAB + lane);
                if (hasHiLg) rh[i] = __ldg(lp + (size_t)(t + 8) * NLAB + lane + 32);
            }

            const ulonglong2* qp = reinterpret_cast<const ulonglong2*>(qsh[par]);
            float Slo, Shi;
            DOT50(eLo, Slo);
            DOT50(eHi, Shi);

            // lag-1 normalizer: exponent of S0, applied next step (exact pow2)
            float S0 = __shfl_sync(0xffffffffu, Slo, 0);

            qsh[par ^ 1][lane] = Slo * ulo;
            if (lane < 19) qsh[par ^ 1][lane + 32] = Shi * uhi;

            Eacc += eprev;
            int be = __float_as_int(S0) >> 23;     // biased exponent (S0 > 0)
            eprev = be - 127;
            sc = __int_as_float((254 - be) << 23); // 2^{-(be-127)}

            __syncwarp();
        }
    }

    // ---- norm = ln2*Eacc + log( sum_k q_len[k] * eT[end=50,k] ) ----
    float normf;
    {
        const ulonglong2* qp = reinterpret_cast<const ulonglong2*>(qsh[len & 1]);
        float Send;
        DOT50(eHi, Send);   // lane 18's eHi row is state 50 = end
        float nf = (float)((double)Eacc * 0.6931471805599453 + (double)__logf(Send));
        normf = __shfl_sync(0xffffffffu, nf, 18);
    }

    // ---- gold = unary + binary (parallel gather) ----
    const int* labp = labels + (size_t)b * S_LEN;
    float acc = 0.0f;
    #pragma unroll 4
    for (int t = lane; t < len; t += 32) {
        int lab = labp[t];
        acc += __ldg(lp + (size_t)t * NLAB + lab);
        int prev = t ? labp[t - 1] : (L - 2);
        acc += __ldg(trans + lab * L + prev);
    }
    if (lane == 0) acc += __ldg(trans + (L - 1) * L + labp[len - 1]);
    #pragma unroll
    for (int o = 16; o; o >>= 1) acc += __shfl_down_sync(0xffffffffu, acc, o);

    if (lane == 0) out[b] = acc - normf;
}

extern "C" void kernel_launch(void* const* d_in, const int* in_sizes, int n_in,
                              void* d_out, int out_size)
{
    const float* logits = (const float*)d_in[0];
    const float* trans  = (const float*)d_in[1];
    const int*   labels = (const int*)d_in[2];
    const int*   lens   = (const int*)d_in[3];
    const int B = in_sizes[3];
    crf_fwd_kernel<<<B, 32>>>(logits, trans, labels, lens, (float*)d_out);
}